// round 3
// baseline (speedup 1.0000x reference)
#include <cuda_runtime.h>
#include <math.h>

// ---------------- problem constants ----------------
#define NN     100000      // nodes
#define EE     1600000     // edges
#define IN_N   128
#define IN_E   64
#define NH     4           // heads
#define FN     32
#define FE     16
#define HFN    128         // NH*FN
#define HFE    64          // NH*FE

// ---------------- scratch (device globals; no allocation allowed) ----------------
__device__ float g_fni [NN * HFE];     // 25.6 MB
__device__ float g_fnj [NN * HFE];     // 25.6 MB
__device__ float g_h   [NN * HFN];     // 51.2 MB  (node proj + b_node)
__device__ float g_eexp[EE * NH];      // 25.6 MB  (unnormalized exp of logits)
__device__ int   g_cnt [NN];           // degree counts -> scatter cursors
__device__ int   g_rowoff[NN + 1];     // CSR row offsets (by dst)
__device__ int   g_perm[EE];           // edge ids sorted by dst
__device__ int   g_psrc[EE];           // src[] gathered in perm order

// ==================================================================
// K0: zero the counters
// ==================================================================
__global__ void zero_cnt_kernel() {
    int i = blockIdx.x * blockDim.x + threadIdx.x;
    if (i < NN) g_cnt[i] = 0;
}

// ==================================================================
// K_deg: in-degree histogram
// ==================================================================
__global__ void deg_kernel(const int* __restrict__ dst) {
    int e = blockIdx.x * blockDim.x + threadIdx.x;
    if (e < EE) atomicAdd(&g_cnt[dst[e]], 1);
}

// ==================================================================
// K_scan: single-block exclusive scan over g_cnt -> g_rowoff, reset
//         g_cnt to the row start (cursor for the scatter pass).
// ==================================================================
__global__ void scan_kernel() {
    __shared__ int wsums[32];
    __shared__ int s_carry;
    int tid = threadIdx.x, lane = tid & 31, wid = tid >> 5;
    if (tid == 0) s_carry = 0;
    __syncthreads();
    for (int base = 0; base < NN; base += 1024) {
        int i = base + tid;
        int v = (i < NN) ? g_cnt[i] : 0;
        // warp inclusive scan
        int x = v;
        #pragma unroll
        for (int o = 1; o < 32; o <<= 1) {
            int y = __shfl_up_sync(0xffffffffu, x, o);
            if (lane >= o) x += y;
        }
        if (lane == 31) wsums[wid] = x;
        __syncthreads();
        if (wid == 0) {
            int s = wsums[lane];
            #pragma unroll
            for (int o = 1; o < 32; o <<= 1) {
                int y = __shfl_up_sync(0xffffffffu, s, o);
                if (lane >= o) s += y;
            }
            wsums[lane] = s;
        }
        __syncthreads();
        int warp_off = (wid == 0) ? 0 : wsums[wid - 1];
        int incl = x + warp_off;
        int excl = incl - v;
        int out = s_carry + excl;
        if (i < NN) { g_rowoff[i] = out; g_cnt[i] = out; }
        __syncthreads();
        if (tid == 1023) s_carry += incl;   // incl of last thread = chunk total
        __syncthreads();
    }
    if (tid == 0) g_rowoff[NN] = s_carry;
}

// ==================================================================
// K_scatter: bucket edges by dst (counting sort)
// ==================================================================
__global__ void scatter_kernel(const int* __restrict__ src,
                               const int* __restrict__ dst) {
    int e = blockIdx.x * blockDim.x + threadIdx.x;
    if (e < EE) {
        int d = dst[e];
        int pos = atomicAdd(&g_cnt[d], 1);
        g_perm[pos] = e;
        g_psrc[pos] = src[e];
    }
}

// ==================================================================
// K1: fused node projections.
//   proj = nfeats @ [W_ni | W_nj | W_node]  (128 -> 256 cols)
//   cols 0..63   -> g_fni
//   cols 64..127 -> g_fnj
//   cols 128..255-> g_h (+ b_node)
// 512 threads: thread = (rowhalf, col); 16 rows x 1 col per thread.
// Full weight matrix (128 KB) staged in dynamic smem, 1 block/SM.
// ==================================================================
#define K1_THREADS 512
__global__ void __launch_bounds__(K1_THREADS)
node_proj_kernel(const float* __restrict__ nfeats,
                 const float* __restrict__ Wnode,
                 const float* __restrict__ bnode,
                 const float* __restrict__ Wni,
                 const float* __restrict__ Wnj)
{
    extern __shared__ float sm[];
    float* sW = sm;                  // [128][256]
    float* sx = sm + 128 * 256;      // [32][128]
    __shared__ float sb[HFN];

    int tid = threadIdx.x;
    for (int i = tid; i < 128 * 256; i += K1_THREADS) {
        int k = i >> 8, c = i & 255;
        float w;
        if (c < 64)        w = Wni[k * 64 + c];
        else if (c < 128)  w = Wnj[k * 64 + (c - 64)];
        else               w = Wnode[k * 128 + (c - 128)];
        sW[i] = w;
    }
    if (tid < HFN) sb[tid] = bnode[tid];
    __syncthreads();

    int c  = tid & 255;
    int r0 = (tid >> 8) * 16;
    const int numTiles = NN / 32;    // 3125, exact

    for (int tile = blockIdx.x; tile < numTiles; tile += gridDim.x) {
        int n0 = tile * 32;
        __syncthreads();             // protect sx reuse
        for (int i = tid * 4; i < 32 * 128; i += K1_THREADS * 4)
            *(float4*)&sx[i] = *(const float4*)&nfeats[n0 * 128 + i];
        __syncthreads();

        float acc[16];
        #pragma unroll
        for (int r = 0; r < 16; r++) acc[r] = 0.f;

        #pragma unroll 4
        for (int k = 0; k < 128; k += 4) {
            float w0 = sW[(k + 0) * 256 + c];
            float w1 = sW[(k + 1) * 256 + c];
            float w2 = sW[(k + 2) * 256 + c];
            float w3 = sW[(k + 3) * 256 + c];
            #pragma unroll
            for (int r = 0; r < 16; r++) {
                float4 xv = *(float4*)&sx[(r0 + r) * 128 + k];
                acc[r] = fmaf(xv.x, w0, acc[r]);
                acc[r] = fmaf(xv.y, w1, acc[r]);
                acc[r] = fmaf(xv.z, w2, acc[r]);
                acc[r] = fmaf(xv.w, w3, acc[r]);
            }
        }

        #pragma unroll
        for (int r = 0; r < 16; r++) {
            int n = n0 + r0 + r;
            float v = acc[r];
            if (c < 64)        g_fni[n * 64 + c] = v;
            else if (c < 128)  g_fnj[n * 64 + (c - 64)] = v;
            else               g_h[n * 128 + (c - 128)] = v + sb[c - 128];
        }
    }
}

// ==================================================================
// K2: fused edge kernel.
//   f_fij = efeats @ W_fij  (64->64), per tile of 32 edges
//   f = leaky_relu(f_fij + f_ni[src] + f_nj[dst] + bias)
//   write f_out; logit_h = sum_{16} f*attn; g_eexp = exp(logit)
// 256 threads: thread = (rowgrp 0..3, col 0..63); 8 edges x 1 col.
// ==================================================================
#define K2_THREADS 256
__global__ void __launch_bounds__(K2_THREADS)
edge_kernel(const float* __restrict__ efeats,
            const int*   __restrict__ src,
            const int*   __restrict__ dst,
            const float* __restrict__ Wfij,
            const float* __restrict__ attn,
            const float* __restrict__ bias,
            float* __restrict__ fout)
{
    __shared__ float sWf[64 * 64];
    __shared__ float sx [32 * 64];
    __shared__ float sattn[HFE];
    __shared__ float sbias[HFE];

    int tid = threadIdx.x;
    for (int i = tid; i < 64 * 64; i += K2_THREADS) sWf[i] = Wfij[i];
    if (tid < HFE) { sattn[tid] = attn[tid]; sbias[tid] = bias[tid]; }
    __syncthreads();

    int c    = tid & 63;
    int rg   = tid >> 6;         // 0..3
    int lane = tid & 31;
    const int numTiles = EE / 32;   // 50000, exact

    for (int tile = blockIdx.x; tile < numTiles; tile += gridDim.x) {
        int e0 = tile * 32;
        __syncthreads();
        for (int i = tid * 4; i < 32 * 64; i += K2_THREADS * 4)
            *(float4*)&sx[i] = *(const float4*)&efeats[e0 * 64 + i];
        __syncthreads();

        float acc[8];
        #pragma unroll
        for (int r = 0; r < 8; r++) acc[r] = 0.f;

        #pragma unroll 4
        for (int k = 0; k < 64; k += 4) {
            float w0 = sWf[(k + 0) * 64 + c];
            float w1 = sWf[(k + 1) * 64 + c];
            float w2 = sWf[(k + 2) * 64 + c];
            float w3 = sWf[(k + 3) * 64 + c];
            #pragma unroll
            for (int r = 0; r < 8; r++) {
                float4 xv = *(float4*)&sx[(rg * 8 + r) * 64 + k];
                acc[r] = fmaf(xv.x, w0, acc[r]);
                acc[r] = fmaf(xv.y, w1, acc[r]);
                acc[r] = fmaf(xv.z, w2, acc[r]);
                acc[r] = fmaf(xv.w, w3, acc[r]);
            }
        }

        #pragma unroll
        for (int r = 0; r < 8; r++) {
            int e = e0 + rg * 8 + r;
            int s = src[e];
            int d = dst[e];
            float f = acc[r] + g_fni[s * 64 + c] + g_fnj[d * 64 + c] + sbias[c];
            f = (f > 0.f) ? f : 0.01f * f;          // leaky_relu(0.01)
            fout[e * 64 + c] = f;
            float p = f * sattn[c];
            p += __shfl_xor_sync(0xffffffffu, p, 1);
            p += __shfl_xor_sync(0xffffffffu, p, 2);
            p += __shfl_xor_sync(0xffffffffu, p, 4);
            p += __shfl_xor_sync(0xffffffffu, p, 8);
            if ((lane & 15) == 0)
                g_eexp[e * 4 + (c >> 4)] = expf(p);
        }
    }
}

// ==================================================================
// K3: per-node aggregation over CSR rows. One warp per node.
//   h_out[n] = (sum_i eexp_i * h[src_i]) / (sum_i eexp_i)  per head
// ==================================================================
__global__ void __launch_bounds__(256)
agg_kernel(float* __restrict__ hout)
{
    int warp = (blockIdx.x * blockDim.x + threadIdx.x) >> 5;
    int lane = threadIdx.x & 31;
    if (warp >= NN) return;

    int beg = g_rowoff[warp];
    int end = g_rowoff[warp + 1];

    float a0 = 0.f, a1 = 0.f, a2 = 0.f, a3 = 0.f;
    float s0 = 0.f, s1 = 0.f, s2 = 0.f, s3 = 0.f;

    for (int i = beg; i < end; i++) {
        int e = g_perm[i];
        int s = g_psrc[i];
        float4 ex = *(float4*)&g_eexp[e * 4];
        const float* hp = &g_h[s * 128];
        a0 = fmaf(ex.x, hp[lane],      a0);
        a1 = fmaf(ex.y, hp[32 + lane], a1);
        a2 = fmaf(ex.z, hp[64 + lane], a2);
        a3 = fmaf(ex.w, hp[96 + lane], a3);
        s0 += ex.x; s1 += ex.y; s2 += ex.z; s3 += ex.w;
    }

    float* op = &hout[warp * 128];
    if (end > beg) {
        op[lane]      = a0 / s0;
        op[32 + lane] = a1 / s1;
        op[64 + lane] = a2 / s2;
        op[96 + lane] = a3 / s3;
    } else {
        op[lane] = 0.f; op[32 + lane] = 0.f;
        op[64 + lane] = 0.f; op[96 + lane] = 0.f;
    }
}

// ==================================================================
// launch
// ==================================================================
extern "C" void kernel_launch(void* const* d_in, const int* in_sizes, int n_in,
                              void* d_out, int out_size)
{
    const float* nfeats = (const float*)d_in[0];
    const float* efeats = (const float*)d_in[1];
    const int*   src    = (const int*)  d_in[2];
    const int*   dst    = (const int*)  d_in[3];
    const float* Wnode  = (const float*)d_in[4];
    const float* bnode  = (const float*)d_in[5];
    const float* Wni    = (const float*)d_in[6];
    const float* Wnj    = (const float*)d_in[7];
    const float* Wfij   = (const float*)d_in[8];
    const float* attn   = (const float*)d_in[9];
    const float* bias   = (const float*)d_in[10];

    float* out  = (float*)d_out;
    float* hout = out;                          // [N*H, FN] = N*128 floats
    float* fout = out + (size_t)NN * HFN;       // [E*H, FE] = E*64 floats

    const int k1_smem = (128 * 256 + 32 * 128) * (int)sizeof(float);  // 147456
    cudaFuncSetAttribute(node_proj_kernel,
                         cudaFuncAttributeMaxDynamicSharedMemorySize, k1_smem);

    // CSR build (independent of GEMMs)
    zero_cnt_kernel<<<(NN + 255) / 256, 256>>>();
    deg_kernel<<<(EE + 255) / 256, 256>>>(dst);
    scan_kernel<<<1, 1024>>>();
    scatter_kernel<<<(EE + 255) / 256, 256>>>(src, dst);

    // projections
    node_proj_kernel<<<148, K1_THREADS, k1_smem>>>(nfeats, Wnode, bnode, Wni, Wnj);

    // fused edge pass
    edge_kernel<<<1480, K2_THREADS>>>(efeats, src, dst, Wfij, attn, bias, fout);

    // aggregation
    agg_kernel<<<(NN * 32 + 255) / 256, 256>>>(hout);
}

// round 5
// speedup vs baseline: 1.2155x; 1.2155x over previous
#include <cuda_runtime.h>
#include <cuda_bf16.h>
#include <math.h>
#include <stdint.h>

// ---------------- problem constants ----------------
#define NN     100000      // nodes
#define EE     1600000     // edges
#define NH     4           // heads
#define FN     32
#define FE     16
#define HFN    128         // NH*FN
#define HFE    64          // NH*FE

// ---------------- scratch (device globals) ----------------
__device__ float g_fni [NN * HFE];
__device__ float g_fnj [NN * HFE];
__device__ float g_h   [NN * HFN];
__device__ float g_eexp[EE * NH];
__device__ int   g_cnt [NN];
__device__ int   g_rowoff[NN + 1];
__device__ int   g_perm[EE];
__device__ int   g_psrc[EE];

// ================= helpers =================
__device__ __forceinline__ uint32_t smem_u32(const void* p) {
    uint32_t r;
    asm("{ .reg .u64 t; cvta.to.shared.u64 t, %1; cvt.u32.u64 %0, t; }"
        : "=r"(r) : "l"(p));
    return r;
}
// cutlass Swizzle<3,4,3>: conflict-free ldmatrix on 128B-row atoms
#define SWZ(x) ((x) ^ (((x) >> 3) & 0x70))

#define LDSM4(r0, r1, r2, r3, a) \
    asm volatile("ldmatrix.sync.aligned.m8n8.x4.shared.b16 {%0,%1,%2,%3}, [%4];" \
                 : "=r"(r0), "=r"(r1), "=r"(r2), "=r"(r3) : "r"(a))

#define MMA16816(d, a, b0, b1) \
    asm volatile("mma.sync.aligned.m16n8k16.row.col.f32.bf16.bf16.f32 " \
                 "{%0,%1,%2,%3},{%4,%5,%6,%7},{%8,%9},{%0,%1,%2,%3};" \
                 : "+f"((d)[0]), "+f"((d)[1]), "+f"((d)[2]), "+f"((d)[3]) \
                 : "r"((a)[0]), "r"((a)[1]), "r"((a)[2]), "r"((a)[3]), \
                   "r"(b0), "r"(b1))

// bf16 two-term split: x = hi + lo; only the lo*lo cross term is dropped (~2^-18)
__device__ __forceinline__ void split_bf(float x, unsigned short& h, unsigned short& l) {
    __nv_bfloat16 bh = __float2bfloat16_rn(x);
    h = __bfloat16_as_ushort(bh);
    float r = x - __bfloat162float(bh);
    l = __bfloat16_as_ushort(__float2bfloat16_rn(r));
}
__device__ __forceinline__ void split2pack(float a, float b, uint32_t& hi, uint32_t& lo) {
    unsigned short ha, la, hb, lb;
    split_bf(a, ha, la);
    split_bf(b, hb, lb);
    hi = ((uint32_t)hb << 16) | ha;
    lo = ((uint32_t)lb << 16) | la;
}

// ================= CSR build =================
__global__ void zero_cnt_kernel() {
    int i = blockIdx.x * blockDim.x + threadIdx.x;
    if (i < NN) g_cnt[i] = 0;
}
__global__ void deg_kernel(const int* __restrict__ dst) {
    int e = blockIdx.x * blockDim.x + threadIdx.x;
    if (e < EE) atomicAdd(&g_cnt[dst[e]], 1);
}
__global__ void scan_kernel() {
    __shared__ int wsums[32];
    __shared__ int s_carry;
    int tid = threadIdx.x, lane = tid & 31, wid = tid >> 5;
    if (tid == 0) s_carry = 0;
    __syncthreads();
    for (int base = 0; base < NN; base += 1024) {
        int i = base + tid;
        int v = (i < NN) ? g_cnt[i] : 0;
        int x = v;
        #pragma unroll
        for (int o = 1; o < 32; o <<= 1) {
            int y = __shfl_up_sync(0xffffffffu, x, o);
            if (lane >= o) x += y;
        }
        if (lane == 31) wsums[wid] = x;
        __syncthreads();
        if (wid == 0) {
            int s = wsums[lane];
            #pragma unroll
            for (int o = 1; o < 32; o <<= 1) {
                int y = __shfl_up_sync(0xffffffffu, s, o);
                if (lane >= o) s += y;
            }
            wsums[lane] = s;
        }
        __syncthreads();
        int warp_off = (wid == 0) ? 0 : wsums[wid - 1];
        int incl = x + warp_off;
        int out = s_carry + incl - v;
        if (i < NN) { g_rowoff[i] = out; g_cnt[i] = out; }
        __syncthreads();
        if (tid == 1023) s_carry += incl;
        __syncthreads();
    }
    if (tid == 0) g_rowoff[NN] = s_carry;
}
__global__ void scatter_kernel(const int* __restrict__ src,
                               const int* __restrict__ dst) {
    int e = blockIdx.x * blockDim.x + threadIdx.x;
    if (e < EE) {
        int d = dst[e];
        int pos = atomicAdd(&g_cnt[d], 1);
        g_perm[pos] = e;
        g_psrc[pos] = src[e];
    }
}

// ================= K1: node projections (mma.sync bf16 3-split) =================
// D[128 rows, 256 cols] = A[128,128] @ W^T[256,128]
// cols 0..63 -> g_fni, 64..127 -> g_fnj, 128..255 -> g_h (+bias)
#define K1_TILES ((NN + 127) / 128)    // 782

__global__ void __launch_bounds__(512, 1)
node_proj_mma(const float* __restrict__ nfeats, const float* __restrict__ Wnode,
              const float* __restrict__ bnode, const float* __restrict__ Wni,
              const float* __restrict__ Wnj)
{
    extern __shared__ unsigned char dynbuf[];
    __shared__ float sbias[HFN];

    uint32_t du = smem_u32(dynbuf);
    uint32_t b0a = (du + 1023u) & ~1023u;
    unsigned char* dp = dynbuf + (b0a - du);
    const uint32_t A_HI = 0, A_LO = 32768, B_HI = 65536, B_LO = 131072;

    int tid = threadIdx.x, lane = tid & 31, wid = tid >> 5;
    int mwarp = wid & 3, nwarp = wid >> 2;
    int lm = lane >> 3, lr = lane & 7;

    if (tid < HFN) sbias[tid] = bnode[tid];

    // Stage fused weights [256 n x 128 k], bf16 hi/lo, SW atoms (128B rows)
    for (int idx = tid; idx < 256 * 128; idx += 512) {
        int n = idx & 255, k = idx >> 8;
        float w;
        if (n < 64)        w = Wni[k * 64 + n];
        else if (n < 128)  w = Wnj[k * 64 + (n - 64)];
        else               w = Wnode[k * 128 + (n - 128)];
        unsigned short h, l;
        split_bf(w, h, l);
        uint32_t off = (uint32_t)((n >> 3) + ((k >> 6) << 5)) * 1024u
                     + (uint32_t)(n & 7) * 128u + ((uint32_t)(k & 63) << 1);
        uint32_t so = SWZ(off);
        *(unsigned short*)(dp + B_HI + so) = h;
        *(unsigned short*)(dp + B_LO + so) = l;
    }

    const uint32_t saHI = b0a + A_HI, saLO = b0a + A_LO;
    const uint32_t sbHI = b0a + B_HI, sbLO = b0a + B_LO;

    for (int tile = blockIdx.x; tile < K1_TILES; tile += gridDim.x) {
        int n0 = tile * 128;
        __syncthreads();
        // stage A tile [128 x 128] fp32 -> bf16 hi/lo
        #pragma unroll
        for (int j = 0; j < 8; j++) {
            int i = j * 512 + tid;          // float4 index 0..4095
            int row = i >> 5;
            int kg  = (i & 31) << 2;
            int n = n0 + row;
            float4 x = make_float4(0.f, 0.f, 0.f, 0.f);
            if (n < NN) x = *(const float4*)&nfeats[(size_t)n * 128 + kg];
            uint32_t h01, l01, h23, l23;
            split2pack(x.x, x.y, h01, l01);
            split2pack(x.z, x.w, h23, l23);
            uint32_t off = (uint32_t)((row >> 3) + ((kg >> 6) << 4)) * 1024u
                         + (uint32_t)(row & 7) * 128u + ((uint32_t)(kg & 63) << 1);
            uint32_t so = SWZ(off);
            *(uint2*)(dp + A_HI + so) = make_uint2(h01, h23);
            *(uint2*)(dp + A_LO + so) = make_uint2(l01, l23);
        }
        __syncthreads();

        float acc[2][8][4];
        #pragma unroll
        for (int mf = 0; mf < 2; mf++)
            #pragma unroll
            for (int nf = 0; nf < 8; nf++)
                #pragma unroll
                for (int q = 0; q < 4; q++) acc[mf][nf][q] = 0.f;

        #pragma unroll
        for (int term = 0; term < 3; term++) {
            uint32_t abase = (term == 2) ? saLO : saHI;
            uint32_t bbase = (term == 1) ? sbLO : sbHI;
            #pragma unroll
            for (int ks = 0; ks < 8; ks++) {
                int k0 = ks * 16;
                uint32_t a[2][4];
                #pragma unroll
                for (int mf = 0; mf < 2; mf++) {
                    int row = mwarp * 32 + mf * 16 + ((lm & 1) << 3) + lr;
                    int kk  = k0 + ((lm >> 1) << 3);
                    uint32_t off = (uint32_t)((row >> 3) + ((kk >> 6) << 4)) * 1024u
                                 + (uint32_t)(row & 7) * 128u + ((uint32_t)(kk & 63) << 1);
                    LDSM4(a[mf][0], a[mf][1], a[mf][2], a[mf][3], abase + SWZ(off));
                }
                uint32_t b[4][4];
                #pragma unroll
                for (int p = 0; p < 4; p++) {
                    int n  = nwarp * 64 + p * 16 + ((lm >> 1) << 3) + lr;
                    int kk = k0 + ((lm & 1) << 3);
                    uint32_t off = (uint32_t)((n >> 3) + ((kk >> 6) << 5)) * 1024u
                                 + (uint32_t)(n & 7) * 128u + ((uint32_t)(kk & 63) << 1);
                    LDSM4(b[p][0], b[p][1], b[p][2], b[p][3], bbase + SWZ(off));
                }
                #pragma unroll
                for (int mf = 0; mf < 2; mf++)
                    #pragma unroll
                    for (int nf = 0; nf < 8; nf++)
                        MMA16816(acc[mf][nf], a[mf],
                                 b[nf >> 1][(nf & 1) * 2], b[nf >> 1][(nf & 1) * 2 + 1]);
            }
        }

        // fragment-layout epilogue
        int rb = n0 + mwarp * 32 + (lane >> 2);
        int cq = (lane & 3) * 2;
        #pragma unroll
        for (int mf = 0; mf < 2; mf++) {
            int r1 = rb + mf * 16, r2 = r1 + 8;
            #pragma unroll
            for (int nf = 0; nf < 8; nf++) {
                int cc = nf * 8 + cq;                  // 0..63 within panel
                float* a4 = acc[mf][nf];
                float2 v1 = make_float2(a4[0], a4[1]);
                float2 v2 = make_float2(a4[2], a4[3]);
                if (nwarp == 0) {
                    if (r1 < NN) *(float2*)&g_fni[(size_t)r1 * 64 + cc] = v1;
                    if (r2 < NN) *(float2*)&g_fni[(size_t)r2 * 64 + cc] = v2;
                } else if (nwarp == 1) {
                    if (r1 < NN) *(float2*)&g_fnj[(size_t)r1 * 64 + cc] = v1;
                    if (r2 < NN) *(float2*)&g_fnj[(size_t)r2 * 64 + cc] = v2;
                } else {
                    int c2 = (nwarp - 2) * 64 + cc;    // 0..127
                    float b0f = sbias[c2], b1f = sbias[c2 + 1];
                    v1.x += b0f; v1.y += b1f;
                    v2.x += b0f; v2.y += b1f;
                    if (r1 < NN) *(float2*)&g_h[(size_t)r1 * 128 + c2] = v1;
                    if (r2 < NN) *(float2*)&g_h[(size_t)r2 * 128 + c2] = v2;
                }
            }
        }
    }
}

// ================= K2: fused edge kernel (mma.sync bf16 3-split) =================
// Per 128-edge tile: D[128,64] = efeats @ Wfij^T; then gather/bias/leaky,
// fout write, per-head logits, exp -> g_eexp.
#define K2_TILES (EE / 128)            // 12500, exact
#define DPITCH   68                    // padded smem D pitch (floats)

__global__ void __launch_bounds__(256, 2)
edge_mma(const float* __restrict__ efeats, const int* __restrict__ src,
         const int* __restrict__ dst, const float* __restrict__ Wfij,
         const float* __restrict__ attn, const float* __restrict__ bias,
         float* __restrict__ fout)
{
    extern __shared__ unsigned char dynbuf[];
    __shared__ float sattn[HFE], sbias[HFE];

    uint32_t du = smem_u32(dynbuf);
    uint32_t b0a = (du + 1023u) & ~1023u;
    unsigned char* dp = dynbuf + (b0a - du);
    const uint32_t A_HI = 0, A_LO = 16384, B_HI = 32768, B_LO = 40960, D_OFF = 49152;
    float* sD = (float*)(dp + D_OFF);   // [128][DPITCH]

    int tid = threadIdx.x, lane = tid & 31, wid = tid >> 5;
    int mwarp = wid & 3, nwarp = wid >> 2;
    int lm = lane >> 3, lr = lane & 7;

    if (tid < HFE) { sattn[tid] = attn[tid]; sbias[tid] = bias[tid]; }

    // Stage Wfij as [n=64][k=64], bf16 hi/lo
    for (int idx = tid; idx < 64 * 64; idx += 256) {
        int n = idx & 63, k = idx >> 6;
        unsigned short h, l;
        split_bf(Wfij[k * 64 + n], h, l);
        uint32_t off = (uint32_t)(n >> 3) * 1024u + (uint32_t)(n & 7) * 128u
                     + ((uint32_t)k << 1);
        uint32_t so = SWZ(off);
        *(unsigned short*)(dp + B_HI + so) = h;
        *(unsigned short*)(dp + B_LO + so) = l;
    }

    const uint32_t saHI = b0a + A_HI, saLO = b0a + A_LO;
    const uint32_t sbHI = b0a + B_HI, sbLO = b0a + B_LO;

    for (int tile = blockIdx.x; tile < K2_TILES; tile += gridDim.x) {
        int e0 = tile * 128;
        __syncthreads();
        // stage A tile [128 edges x 64 feats] fp32 -> bf16 hi/lo
        #pragma unroll
        for (int j = 0; j < 8; j++) {
            int i = j * 256 + tid;          // float4 index 0..2047
            int row = i >> 4;
            int kg  = (i & 15) << 2;
            float4 x = *(const float4*)&efeats[(size_t)(e0 + row) * 64 + kg];
            uint32_t h01, l01, h23, l23;
            split2pack(x.x, x.y, h01, l01);
            split2pack(x.z, x.w, h23, l23);
            uint32_t off = (uint32_t)(row >> 3) * 1024u + (uint32_t)(row & 7) * 128u
                         + ((uint32_t)kg << 1);
            uint32_t so = SWZ(off);
            *(uint2*)(dp + A_HI + so) = make_uint2(h01, h23);
            *(uint2*)(dp + A_LO + so) = make_uint2(l01, l23);
        }
        __syncthreads();

        float acc[2][4][4];
        #pragma unroll
        for (int mf = 0; mf < 2; mf++)
            #pragma unroll
            for (int nf = 0; nf < 4; nf++)
                #pragma unroll
                for (int q = 0; q < 4; q++) acc[mf][nf][q] = 0.f;

        #pragma unroll
        for (int term = 0; term < 3; term++) {
            uint32_t abase = (term == 2) ? saLO : saHI;
            uint32_t bbase = (term == 1) ? sbLO : sbHI;
            #pragma unroll
            for (int ks = 0; ks < 4; ks++) {
                int k0 = ks * 16;
                uint32_t a[2][4];
                #pragma unroll
                for (int mf = 0; mf < 2; mf++) {
                    int row = mwarp * 32 + mf * 16 + ((lm & 1) << 3) + lr;
                    int kk  = k0 + ((lm >> 1) << 3);
                    uint32_t off = (uint32_t)(row >> 3) * 1024u
                                 + (uint32_t)(row & 7) * 128u + ((uint32_t)kk << 1);
                    LDSM4(a[mf][0], a[mf][1], a[mf][2], a[mf][3], abase + SWZ(off));
                }
                uint32_t b[2][4];
                #pragma unroll
                for (int p = 0; p < 2; p++) {
                    int n  = nwarp * 32 + p * 16 + ((lm >> 1) << 3) + lr;
                    int kk = k0 + ((lm & 1) << 3);
                    uint32_t off = (uint32_t)(n >> 3) * 1024u
                                 + (uint32_t)(n & 7) * 128u + ((uint32_t)kk << 1);
                    LDSM4(b[p][0], b[p][1], b[p][2], b[p][3], bbase + SWZ(off));
                }
                #pragma unroll
                for (int mf = 0; mf < 2; mf++)
                    #pragma unroll
                    for (int nf = 0; nf < 4; nf++)
                        MMA16816(acc[mf][nf], a[mf],
                                 b[nf >> 1][(nf & 1) * 2], b[nf >> 1][(nf & 1) * 2 + 1]);
            }
        }

        // accumulators -> smem D
        {
            int rb = mwarp * 32 + (lane >> 2);
            int cq = (lane & 3) * 2;
            #pragma unroll
            for (int mf = 0; mf < 2; mf++) {
                int r1 = rb + mf * 16, r2 = r1 + 8;
                #pragma unroll
                for (int nf = 0; nf < 4; nf++) {
                    int cc = nwarp * 32 + nf * 8 + cq;
                    float* a4 = acc[mf][nf];
                    *(float2*)&sD[r1 * DPITCH + cc] = make_float2(a4[0], a4[1]);
                    *(float2*)&sD[r2 * DPITCH + cc] = make_float2(a4[2], a4[3]);
                }
            }
        }
        __syncthreads();

        // per-edge epilogue: 2 threads per edge, 32 cols (2 heads) each
        int eloc = tid >> 1;
        int half = tid & 1;
        int e = e0 + eloc;
        int sn = src[e], dn = dst[e];
        const float* fni = &g_fni[(size_t)sn * 64 + half * 32];
        const float* fnj = &g_fnj[(size_t)dn * 64 + half * 32];
        float* fo = &fout[(size_t)e * 64 + half * 32];
        const float* dsm = &sD[eloc * DPITCH + half * 32];
        float p0 = 0.f, p1 = 0.f;
        #pragma unroll
        for (int g = 0; g < 8; g++) {
            int c = g * 4;
            float4 dd = *(const float4*)&dsm[c];
            float4 a4 = *(const float4*)&fni[c];
            float4 b4 = *(const float4*)&fnj[c];
            int cb = half * 32 + c;
            float4 o;
            o.x = dd.x + a4.x + b4.x + sbias[cb + 0];
            o.y = dd.y + a4.y + b4.y + sbias[cb + 1];
            o.z = dd.z + a4.z + b4.z + sbias[cb + 2];
            o.w = dd.w + a4.w + b4.w + sbias[cb + 3];
            o.x = (o.x > 0.f) ? o.x : 0.01f * o.x;
            o.y = (o.y > 0.f) ? o.y : 0.01f * o.y;
            o.z = (o.z > 0.f) ? o.z : 0.01f * o.z;
            o.w = (o.w > 0.f) ? o.w : 0.01f * o.w;
            float ph = o.x * sattn[cb + 0] + o.y * sattn[cb + 1]
                     + o.z * sattn[cb + 2] + o.w * sattn[cb + 3];
            if (g < 4) p0 += ph; else p1 += ph;
            *(float4*)&fo[c] = o;
        }
        // unnormalized softmax numerators (shift-invariance: segment-max skipped)
        *(float2*)&g_eexp[(size_t)e * 4 + half * 2] =
            make_float2(expf(p0), expf(p1));
    }
}

// ================= K3: per-node aggregation (warp per node) =================
__global__ void __launch_bounds__(256)
agg_kernel(float* __restrict__ hout)
{
    int warp = (blockIdx.x * blockDim.x + threadIdx.x) >> 5;
    int lane = threadIdx.x & 31;
    if (warp >= NN) return;

    int beg = g_rowoff[warp];
    int end = g_rowoff[warp + 1];

    float a0 = 0.f, a1 = 0.f, a2 = 0.f, a3 = 0.f;
    float s0 = 0.f, s1 = 0.f, s2 = 0.f, s3 = 0.f;

    for (int i = beg; i < end; i++) {
        int e = g_perm[i];
        int s = g_psrc[i];
        float4 ex = *(float4*)&g_eexp[(size_t)e * 4];
        const float* hp = &g_h[(size_t)s * 128];
        a0 = fmaf(ex.x, hp[lane],      a0);
        a1 = fmaf(ex.y, hp[32 + lane], a1);
        a2 = fmaf(ex.z, hp[64 + lane], a2);
        a3 = fmaf(ex.w, hp[96 + lane], a3);
        s0 += ex.x; s1 += ex.y; s2 += ex.z; s3 += ex.w;
    }

    float* op = &hout[(size_t)warp * 128];
    if (end > beg) {
        op[lane]      = a0 / s0;
        op[32 + lane] = a1 / s1;
        op[64 + lane] = a2 / s2;
        op[96 + lane] = a3 / s3;
    } else {
        op[lane] = 0.f; op[32 + lane] = 0.f;
        op[64 + lane] = 0.f; op[96 + lane] = 0.f;
    }
}

// ================= launch =================
extern "C" void kernel_launch(void* const* d_in, const int* in_sizes, int n_in,
                              void* d_out, int out_size)
{
    const float* nfeats = (const float*)d_in[0];
    const float* efeats = (const float*)d_in[1];
    const int*   src    = (const int*)  d_in[2];
    const int*   dst    = (const int*)  d_in[3];
    const float* Wnode  = (const float*)d_in[4];
    const float* bnode  = (const float*)d_in[5];
    const float* Wni    = (const float*)d_in[6];
    const float* Wnj    = (const float*)d_in[7];
    const float* Wfij   = (const float*)d_in[8];
    const float* attn   = (const float*)d_in[9];
    const float* bias   = (const float*)d_in[10];

    float* out  = (float*)d_out;
    float* hout = out;                          // [N*H, FN] = N*128 floats
    float* fout = out + (size_t)NN * HFN;       // [E*H, FE] = E*64 floats

    const int k1_smem = 192 * 1024 + 1024;                    // 197632
    const int k2_smem = 48 * 1024 + 128 * DPITCH * 4 + 1024;  // 85120
    cudaFuncSetAttribute(node_proj_mma,
                         cudaFuncAttributeMaxDynamicSharedMemorySize, k1_smem);
    cudaFuncSetAttribute(edge_mma,
                         cudaFuncAttributeMaxDynamicSharedMemorySize, k2_smem);

    // CSR build
    zero_cnt_kernel<<<(NN + 255) / 256, 256>>>();
    deg_kernel<<<(EE + 255) / 256, 256>>>(dst);
    scan_kernel<<<1, 1024>>>();
    scatter_kernel<<<(EE + 255) / 256, 256>>>(src, dst);

    // tensor-core projections + fused edge pass
    node_proj_mma<<<148, 512, k1_smem>>>(nfeats, Wnode, bnode, Wni, Wnj);
    edge_mma<<<296, 256, k2_smem>>>(efeats, src, dst, Wfij, attn, bias, fout);

    // aggregation
    agg_kernel<<<(NN * 32 + 255) / 256, 256>>>(hout);
}